// round 16
// baseline (speedup 1.0000x reference)
#include <cuda_runtime.h>
#include <cuda_bf16.h>
#include <cuda_fp16.h>
#include <cstdint>

#define BATCH 8
#define NF 2048
#define NK 4096
#define NT 6144
#define CIN 256
#define CKQ 64
#define COUT 256

// ---- packed scratch (static __device__; no runtime alloc) ----
__device__ __half g_q[BATCH * NF * CKQ];           //  2 MB (q*0.125, fp16)
__device__ __half g_k[BATCH * NK * CKQ];           //  4 MB (fp16)
__device__ __half g_vt[BATCH * COUT * NK];         // 16 MB (V^T fp16: [b][n][key])
__device__ __nv_bfloat16 g_fhi[BATCH * NT * CIN];  // 25 MB
__device__ __nv_bfloat16 g_flo[BATCH * NT * CIN];  // 25 MB

__device__ __forceinline__ void split2(float x, float& hi, float& lo) {
    __nv_bfloat16 h = __float2bfloat16(x);
    hi = __bfloat162float(h);
    lo = x - hi;
}
__device__ __forceinline__ uint32_t pkbf(float a, float b) {
    uint32_t r;
    asm("cvt.rn.bf16x2.f32 %0, %1, %2;" : "=r"(r) : "f"(b), "f"(a));
    return r;
}
__device__ __forceinline__ uint32_t pkhf(float a, float b) {
    __half2 h = __floats2half2_rn(a, b);
    return *(uint32_t*)&h;
}
__device__ __forceinline__ uint32_t smem_u32(const void* p) {
    uint32_t a;
    asm("{ .reg .u64 t; cvta.to.shared.u64 t, %1; cvt.u32.u64 %0, t; }" : "=r"(a) : "l"(p));
    return a;
}
__device__ __forceinline__ void cp16(uint32_t smem, const void* g) {
    asm volatile("cp.async.cg.shared.global [%0], [%1], 16;" :: "r"(smem), "l"(g));
}
#define CP_COMMIT() asm volatile("cp.async.commit_group;" ::: "memory")
#define CP_WAIT0()  asm volatile("cp.async.wait_group 0;" ::: "memory")

#define LDSM4(r0, r1, r2, r3, addr) \
    asm volatile("ldmatrix.sync.aligned.m8n8.x4.shared.b16 {%0,%1,%2,%3}, [%4];" \
        : "=r"(r0), "=r"(r1), "=r"(r2), "=r"(r3) : "r"(addr))

#define MMA_BF16(d, a, b0, b1) \
    asm volatile("mma.sync.aligned.m16n8k16.row.col.f32.bf16.bf16.f32 " \
        "{%0,%1,%2,%3}, {%4,%5,%6,%7}, {%8,%9}, {%0,%1,%2,%3};" \
        : "+f"((d)[0]), "+f"((d)[1]), "+f"((d)[2]), "+f"((d)[3]) \
        : "r"((a)[0]), "r"((a)[1]), "r"((a)[2]), "r"((a)[3]), "r"(b0), "r"(b1))

#define MMA_F16H(d, a, b0, b1) \
    asm volatile("mma.sync.aligned.m16n8k16.row.col.f32.f16.f16.f32 " \
        "{%0,%1,%2,%3}, {%4,%5,%6,%7}, {%8,%9}, {%0,%1,%2,%3};" \
        : "+f"((d)[0]), "+f"((d)[1]), "+f"((d)[2]), "+f"((d)[3]) \
        : "r"((a)[0]), "r"((a)[1]), "r"((a)[2]), "r"((a)[3]), "r"(b0), "r"(b1))

// ============================================================
// feat fp32 -> bf16 hi/lo, fused with keep-row passthrough copy
// ============================================================
__global__ __launch_bounds__(512) void convert_copy_kernel(
    const float* __restrict__ feat, float* __restrict__ out)
{
    size_t i = (size_t)blockIdx.x * 512 + threadIdx.x;   // float4 index
    float4 v = ((const float4*)feat)[i];
    float h0,l0,h1,l1,h2,l2,h3,l3;
    split2(v.x,h0,l0); split2(v.y,h1,l1); split2(v.z,h2,l2); split2(v.w,h3,l3);
    ((uint2*)g_fhi)[i] = make_uint2(pkbf(h0,h1), pkbf(h2,h3));
    ((uint2*)g_flo)[i] = make_uint2(pkbf(l0,l1), pkbf(l2,l3));
    size_t tok = i >> 6;
    if ((tok % NT) >= NF) ((float4*)out)[i] = v;
}

// ============================================================
// Unified tensor-core projection: each CTA = 128 tokens x 64 outs, K=256
// grid: [0,128) Q | [128,384) K | [384,1408) V
// Q/K: 3-term bf16 MMA, fp16 output; V: 2-term, fp16 output
// ============================================================
#define PSM_WHI 0
#define PSM_WLO 32768
#define PSM_A   65536
#define PSM_BYTES 131072
#define VS_PITCH 66

__global__ __launch_bounds__(512, 1) void proj_mma_kernel(
    const float* __restrict__ Wq, const float* __restrict__ bq,
    const float* __restrict__ Wk, const float* __restrict__ bk,
    const float* __restrict__ Wv, const float* __restrict__ bv)
{
    extern __shared__ __align__(1024) char smem[];
    uint32_t sb = smem_u32(smem);
    const int tid  = threadIdx.x;
    const int lane = tid & 31;
    const int w    = tid >> 5;
    const int wblk = w >> 1;
    const int f    = w & 1;
    const int g    = lane >> 2;
    const int t    = lane & 3;

    const int amrow = wblk * 16 + ((lane >> 3) & 1) * 8 + (lane & 7);
    const int aksel = lane >> 4;
    const int brow8 = ((lane >> 4) & 1) * 8 + (lane & 7);
    const int bksel = (lane >> 3) & 1;

    int bid = blockIdx.x;
    int mode, b, tok0, n0 = 0;
    const float *W, *bias;
    if (bid < 128)      { mode = 0; b = bid >> 4; tok0 = b * NT + (bid & 15) * 128;        W = Wq; bias = bq; }
    else if (bid < 384) { int u = bid - 128; mode = 1; b = u >> 5; tok0 = b * NT + NF + (u & 31) * 128; W = Wk; bias = bk; }
    else                { int u = bid - 384; int kt = u >> 2; mode = 2; b = kt >> 5;
                          tok0 = b * NT + NF + (kt & 31) * 128; n0 = (u & 3) * 64;
                          W = Wv + (size_t)n0 * CIN; bias = bv + n0; }
    const bool three = (mode != 2);

#pragma unroll
    for (int i = tid; i < 64 * 64; i += 512) {
        int n = i >> 6, c = i & 63;
        float4 wv = *(const float4*)&W[(size_t)n * CIN + c * 4];
        float h0,l0,h1,l1,h2,l2,h3,l3;
        split2(wv.x,h0,l0); split2(wv.y,h1,l1); split2(wv.z,h2,l2); split2(wv.w,h3,l3);
        uint32_t off = (uint32_t)(n * 512) + ((((c >> 1) ^ (n & 7))) << 4) + (c & 1) * 8;
        *(uint2*)(smem + PSM_WHI + off) = make_uint2(pkbf(h0,h1), pkbf(h2,h3));
        *(uint2*)(smem + PSM_WLO + off) = make_uint2(pkbf(l0,l1), pkbf(l2,l3));
    }

    auto prefetch_a = [&](int buf, int kc) {
#pragma unroll
        for (int i = tid; i < 2048; i += 512) {
            int hl = i >> 10, r = (i >> 3) & 127, c = i & 7;
            const char* src = (hl ? (const char*)g_flo : (const char*)g_fhi)
                            + (((size_t)(tok0 + r)) << 9) + (kc << 7) + (c << 4);
            uint32_t dst = sb + PSM_A + (uint32_t)(hl * 2 + buf) * 16384
                         + (uint32_t)(r << 7) + (uint32_t)((c ^ (r & 7)) << 4);
            cp16(dst, src);
        }
    };

    float oacc[4][4];
#pragma unroll
    for (int i = 0; i < 4; i++)
#pragma unroll
        for (int j = 0; j < 4; j++) oacc[i][j] = 0.0f;

    prefetch_a(0, 0);
    CP_COMMIT();
    __syncthreads();

    for (int kc = 0; kc < 4; kc++) {
        int buf = kc & 1;
        CP_WAIT0();
        __syncthreads();
        if (kc + 1 < 4) prefetch_a(buf ^ 1, kc + 1);
        CP_COMMIT();

#pragma unroll
        for (int kt = 0; kt < 4; kt++) {
            uint32_t ah[4], al[4];
            {
                int c = kt * 2 + aksel;
                uint32_t aaddr = sb + PSM_A + (uint32_t)buf * 16384
                               + amrow * 128 + ((c ^ (amrow & 7)) << 4);
                LDSM4(ah[0], ah[1], ah[2], ah[3], aaddr);
                if (three) LDSM4(al[0], al[1], al[2], al[3], aaddr + 32768);
            }
#pragma unroll
            for (int nn = 0; nn < 2; nn++) {
                uint32_t bh[4], bl[4];
                int n = f * 32 + nn * 16 + brow8;
                int c = kc * 8 + kt * 2 + bksel;
                uint32_t baddr = sb + PSM_WHI + n * 512 + ((c ^ (n & 7)) << 4);
                LDSM4(bh[0], bh[1], bh[2], bh[3], baddr);
                LDSM4(bl[0], bl[1], bl[2], bl[3], baddr + 32768);
#pragma unroll
                for (int j = 0; j < 2; j++) {
                    float* o = oacc[nn * 2 + j];
                    MMA_BF16(o, ah, bh[2*j], bh[2*j+1]);
                    MMA_BF16(o, ah, bl[2*j], bl[2*j+1]);
                    if (three) MMA_BF16(o, al, bh[2*j], bh[2*j+1]);
                }
            }
        }
    }

    int pos = tok0 - b * NT;
    if (mode == 0) {
        int qrow = b * NF + pos + wblk * 16 + g;
#pragma unroll
        for (int nn = 0; nn < 2; nn++)
#pragma unroll
            for (int j = 0; j < 2; j++) {
                float* o = oacc[nn * 2 + j];
                int n = f * 32 + nn * 16 + j * 8 + 2 * t;
                float bi0 = bias[n], bi1 = bias[n + 1];
                *(uint32_t*)&g_q[((size_t)qrow << 6) + n] =
                    pkhf((o[0] + bi0) * 0.125f, (o[1] + bi1) * 0.125f);
                *(uint32_t*)&g_q[((size_t)(qrow + 8) << 6) + n] =
                    pkhf((o[2] + bi0) * 0.125f, (o[3] + bi1) * 0.125f);
            }
    } else if (mode == 1) {
        int krow = b * NK + (pos - NF) + wblk * 16 + g;
#pragma unroll
        for (int nn = 0; nn < 2; nn++)
#pragma unroll
            for (int j = 0; j < 2; j++) {
                float* o = oacc[nn * 2 + j];
                int n = f * 32 + nn * 16 + j * 8 + 2 * t;
                float bi0 = bias[n], bi1 = bias[n + 1];
                *(uint32_t*)&g_k[((size_t)krow << 6) + n] = pkhf(o[0] + bi0, o[1] + bi1);
                *(uint32_t*)&g_k[((size_t)(krow + 8) << 6) + n] = pkhf(o[2] + bi0, o[3] + bi1);
            }
    } else {
        __syncthreads();
        __half* vs = (__half*)(smem + PSM_A);
        int row = wblk * 16 + g;
#pragma unroll
        for (int nn = 0; nn < 2; nn++)
#pragma unroll
            for (int j = 0; j < 2; j++) {
                float* o = oacc[nn * 2 + j];
                int n = f * 32 + nn * 16 + j * 8 + 2 * t;
                float bi0 = bias[n], bi1 = bias[n + 1];
                *(uint32_t*)&vs[row * VS_PITCH + n]       = pkhf(o[0] + bi0, o[1] + bi1);
                *(uint32_t*)&vs[(row + 8) * VS_PITCH + n] = pkhf(o[2] + bi0, o[3] + bi1);
            }
        __syncthreads();
        int n = tid >> 3, part = tid & 7;
        int key0 = pos - NF;
        uint32_t pk[8];
#pragma unroll
        for (int j = 0; j < 8; j++) {
            __half a = vs[(part * 16 + 2 * j) * VS_PITCH + n];
            __half bq2 = vs[(part * 16 + 2 * j + 1) * VS_PITCH + n];
            __half2 h2v = __halves2half2(a, bq2);
            pk[j] = *(uint32_t*)&h2v;
        }
        __half* dst = g_vt + (((size_t)(b * COUT + n0 + n)) << 12) + key0 + part * 16;
        *(uint4*)dst       = make_uint4(pk[0], pk[1], pk[2], pk[3]);
        *(uint4*)(dst + 8) = make_uint4(pk[4], pk[5], pk[6], pk[7]);
    }
}

// ============================================================
// mma.sync flash attention — KT=64, all-fp16 operands
//   QK: fp16 single MMA; PV: fp16 single-term
// ============================================================
#define KT 64
#define NBLK (NK / KT)

#define SM_Q     0            /* 16384 (fp16 Q, 128B rows, swizzled) */
#define SM_K     16384        /* 2 x 8192 (fp16 K) */
#define SM_V     32768        /* 2 x 32768 (fp16 V^T, 128B rows, swizzled) */
#define SM_P     98304        /* 128 x 128B, swizzled */
#define SM_LACC  114688       /* 2 x 128 floats */
#define SM_BYTES 115712

__device__ __forceinline__ void prefetch_kv(uint32_t sb, int buf, int bb, int kb)
{
    int tid = threadIdx.x;
    {   // K: 64 rows x 8 chunks = 512, one per thread
        int r = tid >> 3, c = tid & 7;
        const char* src = (const char*)g_k
                        + (((size_t)(bb * NK + kb * KT + r)) << 7) + (c << 4);
        uint32_t dst = sb + SM_K + (uint32_t)buf * 8192
                     + (uint32_t)(r << 7) + (uint32_t)((c ^ (r & 7)) << 4);
        cp16(dst, src);
    }
#pragma unroll
    for (int i = 0; i < 4; i++) {        // V^T: 256 rows x 8 chunks
        int idx = tid + i * 512;
        int n = (idx >> 3) & 255, c = idx & 7;
        const char* src = (const char*)g_vt
                        + (((size_t)(bb * COUT + n)) << 13) + (kb << 7) + (c << 4);
        uint32_t dst = sb + SM_V + (uint32_t)buf * 32768
                     + (uint32_t)(n << 7) + (uint32_t)((c ^ (n & 7)) << 4);
        cp16(dst, src);
    }
}

__global__ __launch_bounds__(512, 1) void attn_mma_kernel(float* __restrict__ out)
{
    extern __shared__ __align__(1024) char smem[];
    uint32_t sb = smem_u32(smem);
    const int tid  = threadIdx.x;
    const int lane = tid & 31;
    const int w    = tid >> 5;
    const int wblk = w >> 1;
    const int f    = w & 1;
    const int g    = lane >> 2;
    const int t    = lane & 3;
    const int bb   = blockIdx.x >> 4;
    const int qt   = blockIdx.x & 15;

    const int amrow = wblk * 16 + ((lane >> 3) & 1) * 8 + (lane & 7);
    const int aksel = lane >> 4;
    const int brow8 = ((lane >> 4) & 1) * 8 + (lane & 7);
    const int bksel = (lane >> 3) & 1;

    // ---- stage Q (fp16) into smem, swizzled ----
#pragma unroll
    for (int i = tid; i < 1024; i += 512) {
        int r = i >> 3, c = i & 7;
        const char* src = (const char*)g_q
                        + (((size_t)(bb * NF + qt * 128 + r)) << 7) + (c << 4);
        uint4 v = *(const uint4*)src;
        *(uint4*)(smem + SM_Q + r * 128 + ((c ^ (r & 7)) << 4)) = v;
    }

    float oacc[16][4];
#pragma unroll
    for (int i = 0; i < 16; i++)
#pragma unroll
        for (int j = 0; j < 4; j++) oacc[i][j] = 0.0f;
    float lacc0 = 0.0f, lacc1 = 0.0f;

    prefetch_kv(sb, 0, bb, 0);
    CP_COMMIT();

    for (int i = 0; i < NBLK; i++) {
        int buf = i & 1;
        CP_WAIT0();
        __syncthreads();

        if (i + 1 < NBLK) prefetch_kv(sb, buf ^ 1, bb, i + 1);
        CP_COMMIT();

        // ---- QK: S[16 x 32keys] = Q * K (fp16 single term) ----
        float sacc[4][4];
#pragma unroll
        for (int nt = 0; nt < 4; nt++)
#pragma unroll
            for (int j = 0; j < 4; j++) sacc[nt][j] = 0.0f;

#pragma unroll
        for (int kt = 0; kt < 4; kt++) {
            uint32_t ah[4];
            {
                int kc = kt * 2 + aksel;
                uint32_t aaddr = sb + SM_Q + amrow * 128 + ((kc ^ (amrow & 7)) << 4);
                LDSM4(ah[0], ah[1], ah[2], ah[3], aaddr);
            }
#pragma unroll
            for (int u = 0; u < 2; u++) {
                uint32_t bh[4];
                int r  = f * 32 + u * 16 + brow8;
                int kc = kt * 2 + bksel;
                uint32_t baddr = sb + SM_K + (uint32_t)buf * 8192
                               + (r << 7) + ((kc ^ (r & 7)) << 4);
                LDSM4(bh[0], bh[1], bh[2], bh[3], baddr);
#pragma unroll
                for (int v = 0; v < 2; v++) {
                    MMA_F16H(sacc[u * 2 + v], ah, bh[2*v], bh[2*v+1]);
                }
            }
        }

        // ---- exp + fp16 store, swizzled 128B-pitch P ----
        {
            int m0 = wblk * 16 + g;
#pragma unroll
            for (int nt = 0; nt < 4; nt++) {
                float p0 = __expf(sacc[nt][0]);
                float p1 = __expf(sacc[nt][1]);
                float p2 = __expf(sacc[nt][2]);
                float p3 = __expf(sacc[nt][3]);
                lacc0 += p0 + p1;
                lacc1 += p2 + p3;
                int c = f * 4 + nt;
                *(uint32_t*)(smem + SM_P + m0 * 128
                             + ((c ^ (m0 & 7)) << 4) + 4 * t) = pkhf(p0, p1);
                *(uint32_t*)(smem + SM_P + (m0 + 8) * 128
                             + ((c ^ (m0 & 7)) << 4) + 4 * t) = pkhf(p2, p3);
            }
        }
        __syncthreads();

        // ---- PV: O[16 x 128] += P * V (fp16 single term) ----
#pragma unroll
        for (int kt = 0; kt < 4; kt++) {
            uint32_t ph[4];
            {
                int kc = kt * 2 + aksel;
                uint32_t paddr = sb + SM_P + amrow * 128 + ((kc ^ (amrow & 7)) << 4);
                LDSM4(ph[0], ph[1], ph[2], ph[3], paddr);
            }
#pragma unroll
            for (int p = 0; p < 8; p++) {
                uint32_t bh[4];
                int n  = f * 128 + p * 16 + brow8;
                int kc = kt * 2 + bksel;
                uint32_t vaddr = sb + SM_V + (uint32_t)buf * 32768
                               + (n << 7) + ((kc ^ (n & 7)) << 4);
                LDSM4(bh[0], bh[1], bh[2], bh[3], vaddr);
#pragma unroll
                for (int j = 0; j < 2; j++) {
                    MMA_F16H(oacc[p * 2 + j], ph, bh[2*j], bh[2*j+1]);
                }
            }
        }
    }

    lacc0 += __shfl_xor_sync(0xFFFFFFFFu, lacc0, 1);
    lacc0 += __shfl_xor_sync(0xFFFFFFFFu, lacc0, 2);
    lacc1 += __shfl_xor_sync(0xFFFFFFFFu, lacc1, 1);
    lacc1 += __shfl_xor_sync(0xFFFFFFFFu, lacc1, 2);
    float* LACC = (float*)(smem + SM_LACC);
    if (t == 0) {
        LACC[f * 128 + wblk * 16 + g]     = lacc0;
        LACC[f * 128 + wblk * 16 + g + 8] = lacc1;
    }
    __syncthreads();
    int m0 = wblk * 16 + g;
    float linv0 = 1.0f / (LACC[m0]     + LACC[128 + m0]);
    float linv1 = 1.0f / (LACC[m0 + 8] + LACC[128 + m0 + 8]);

    float* op = out + ((size_t)(bb * NT) + qt * 128) * COUT;
#pragma unroll
    for (int p = 0; p < 16; p++) {
        int col = f * 128 + p * 8 + 2 * t;
        float2 v0 = make_float2(oacc[p][0] * linv0, oacc[p][1] * linv0);
        float2 v1 = make_float2(oacc[p][2] * linv1, oacc[p][3] * linv1);
        *(float2*)&op[(size_t)m0 * COUT + col]       = v0;
        *(float2*)&op[(size_t)(m0 + 8) * COUT + col] = v1;
    }
}

// ============================================================
extern "C" void kernel_launch(void* const* d_in, const int* in_sizes, int n_in,
                              void* d_out, int out_size)
{
    const float* feat = (const float*)d_in[0];
    const float* Wq = (const float*)d_in[2];
    const float* bq = (const float*)d_in[3];
    const float* Wk = (const float*)d_in[4];
    const float* bk = (const float*)d_in[5];
    const float* Wv = (const float*)d_in[6];
    const float* bv = (const float*)d_in[7];
    float* out = (float*)d_out;

    cudaFuncSetAttribute(attn_mma_kernel, cudaFuncAttributeMaxDynamicSharedMemorySize, SM_BYTES);
    cudaFuncSetAttribute(proj_mma_kernel, cudaFuncAttributeMaxDynamicSharedMemorySize, PSM_BYTES);

    convert_copy_kernel<<<6144, 512>>>(feat, out);
    proj_mma_kernel<<<1408, 512, PSM_BYTES>>>(Wq, bq, Wk, bk, Wv, bv);
    attn_mma_kernel<<<BATCH * (NF / 128), 512, SM_BYTES>>>(out);
}

// round 17
// speedup vs baseline: 1.5104x; 1.5104x over previous
#include <cuda_runtime.h>
#include <cuda_bf16.h>
#include <cuda_fp16.h>
#include <cstdint>

#define BATCH 8
#define NF 2048
#define NK 4096
#define NT 6144
#define CIN 256
#define CKQ 64
#define COUT 256

// ---- packed scratch (static __device__; no runtime alloc) ----
__device__ __half g_q[BATCH * NF * CKQ];           //  2 MB (q*0.125, fp16)
__device__ __half g_k[BATCH * NK * CKQ];           //  4 MB (fp16)
__device__ __half g_vt[BATCH * COUT * NK];         // 16 MB (V^T fp16: [b][n][key])
__device__ __nv_bfloat16 g_fhi[BATCH * NT * CIN];  // 25 MB
__device__ __nv_bfloat16 g_flo[BATCH * NT * CIN];  // 25 MB

__device__ __forceinline__ void split2(float x, float& hi, float& lo) {
    __nv_bfloat16 h = __float2bfloat16(x);
    hi = __bfloat162float(h);
    lo = x - hi;
}
__device__ __forceinline__ uint32_t pkbf(float a, float b) {
    uint32_t r;
    asm("cvt.rn.bf16x2.f32 %0, %1, %2;" : "=r"(r) : "f"(b), "f"(a));
    return r;
}
__device__ __forceinline__ uint32_t pkhf(float a, float b) {
    __half2 h = __floats2half2_rn(a, b);
    return *(uint32_t*)&h;
}
__device__ __forceinline__ uint32_t smem_u32(const void* p) {
    uint32_t a;
    asm("{ .reg .u64 t; cvta.to.shared.u64 t, %1; cvt.u32.u64 %0, t; }" : "=r"(a) : "l"(p));
    return a;
}
__device__ __forceinline__ void cp16(uint32_t smem, const void* g) {
    asm volatile("cp.async.cg.shared.global [%0], [%1], 16;" :: "r"(smem), "l"(g));
}
#define CP_COMMIT() asm volatile("cp.async.commit_group;" ::: "memory")
#define CP_WAIT0()  asm volatile("cp.async.wait_group 0;" ::: "memory")

// streaming 16B store (evict-first: write-once data, don't pollute L2)
__device__ __forceinline__ void stcs16(void* p, uint2 a, uint2 b) {
    asm volatile("st.global.cs.v4.u32 [%0], {%1,%2,%3,%4};"
                 :: "l"(p), "r"(a.x), "r"(a.y), "r"(b.x), "r"(b.y));
}

#define LDSM4(r0, r1, r2, r3, addr) \
    asm volatile("ldmatrix.sync.aligned.m8n8.x4.shared.b16 {%0,%1,%2,%3}, [%4];" \
        : "=r"(r0), "=r"(r1), "=r"(r2), "=r"(r3) : "r"(addr))

#define MMA_BF16(d, a, b0, b1) \
    asm volatile("mma.sync.aligned.m16n8k16.row.col.f32.bf16.bf16.f32 " \
        "{%0,%1,%2,%3}, {%4,%5,%6,%7}, {%8,%9}, {%0,%1,%2,%3};" \
        : "+f"((d)[0]), "+f"((d)[1]), "+f"((d)[2]), "+f"((d)[3]) \
        : "r"((a)[0]), "r"((a)[1]), "r"((a)[2]), "r"((a)[3]), "r"(b0), "r"(b1))

#define MMA_F16H(d, a, b0, b1) \
    asm volatile("mma.sync.aligned.m16n8k16.row.col.f32.f16.f16.f32 " \
        "{%0,%1,%2,%3}, {%4,%5,%6,%7}, {%8,%9}, {%0,%1,%2,%3};" \
        : "+f"((d)[0]), "+f"((d)[1]), "+f"((d)[2]), "+f"((d)[3]) \
        : "r"((a)[0]), "r"((a)[1]), "r"((a)[2]), "r"((a)[3]), "r"(b0), "r"(b1))

// ============================================================
// feat fp32 -> bf16 hi/lo, fused with keep-row passthrough copy
// ============================================================
__global__ __launch_bounds__(512) void convert_copy_kernel(
    const float* __restrict__ feat, float* __restrict__ out)
{
    size_t i = (size_t)blockIdx.x * 512 + threadIdx.x;   // float4 index
    float4 v = ((const float4*)feat)[i];
    float h0,l0,h1,l1,h2,l2,h3,l3;
    split2(v.x,h0,l0); split2(v.y,h1,l1); split2(v.z,h2,l2); split2(v.w,h3,l3);
    // hi is re-read 3x by proj (keep cacheable); lo re-read too. out is write-once.
    ((uint2*)g_fhi)[i] = make_uint2(pkbf(h0,h1), pkbf(h2,h3));
    ((uint2*)g_flo)[i] = make_uint2(pkbf(l0,l1), pkbf(l2,l3));
    size_t tok = i >> 6;
    if ((tok % NT) >= NF) {
        float4* dst = &((float4*)out)[i];
        asm volatile("st.global.cs.v4.f32 [%0], {%1,%2,%3,%4};"
                     :: "l"(dst), "f"(v.x), "f"(v.y), "f"(v.z), "f"(v.w));
    }
}

// ============================================================
// Unified tensor-core projection: each CTA = 128 tokens x 64 outs, K=256
// grid: [0,128) Q | [128,384) K | [384,1408) V
// Q/K: 3-term bf16 MMA, fp16 output; V: 2-term, fp16 output
// ============================================================
#define PSM_WHI 0
#define PSM_WLO 32768
#define PSM_A   65536
#define PSM_BYTES 131072
#define VS_PITCH 66

__global__ __launch_bounds__(512, 1) void proj_mma_kernel(
    const float* __restrict__ Wq, const float* __restrict__ bq,
    const float* __restrict__ Wk, const float* __restrict__ bk,
    const float* __restrict__ Wv, const float* __restrict__ bv)
{
    extern __shared__ __align__(1024) char smem[];
    uint32_t sb = smem_u32(smem);
    const int tid  = threadIdx.x;
    const int lane = tid & 31;
    const int w    = tid >> 5;
    const int wblk = w >> 1;
    const int f    = w & 1;
    const int g    = lane >> 2;
    const int t    = lane & 3;

    const int amrow = wblk * 16 + ((lane >> 3) & 1) * 8 + (lane & 7);
    const int aksel = lane >> 4;
    const int brow8 = ((lane >> 4) & 1) * 8 + (lane & 7);
    const int bksel = (lane >> 3) & 1;

    int bid = blockIdx.x;
    int mode, b, tok0, n0 = 0;
    const float *W, *bias;
    if (bid < 128)      { mode = 0; b = bid >> 4; tok0 = b * NT + (bid & 15) * 128;        W = Wq; bias = bq; }
    else if (bid < 384) { int u = bid - 128; mode = 1; b = u >> 5; tok0 = b * NT + NF + (u & 31) * 128; W = Wk; bias = bk; }
    else                { int u = bid - 384; int kt = u >> 2; mode = 2; b = kt >> 5;
                          tok0 = b * NT + NF + (kt & 31) * 128; n0 = (u & 3) * 64;
                          W = Wv + (size_t)n0 * CIN; bias = bv + n0; }
    const bool three = (mode != 2);

#pragma unroll
    for (int i = tid; i < 64 * 64; i += 512) {
        int n = i >> 6, c = i & 63;
        float4 wv = *(const float4*)&W[(size_t)n * CIN + c * 4];
        float h0,l0,h1,l1,h2,l2,h3,l3;
        split2(wv.x,h0,l0); split2(wv.y,h1,l1); split2(wv.z,h2,l2); split2(wv.w,h3,l3);
        uint32_t off = (uint32_t)(n * 512) + ((((c >> 1) ^ (n & 7))) << 4) + (c & 1) * 8;
        *(uint2*)(smem + PSM_WHI + off) = make_uint2(pkbf(h0,h1), pkbf(h2,h3));
        *(uint2*)(smem + PSM_WLO + off) = make_uint2(pkbf(l0,l1), pkbf(l2,l3));
    }

    auto prefetch_a = [&](int buf, int kc) {
#pragma unroll
        for (int i = tid; i < 2048; i += 512) {
            int hl = i >> 10, r = (i >> 3) & 127, c = i & 7;
            const char* src = (hl ? (const char*)g_flo : (const char*)g_fhi)
                            + (((size_t)(tok0 + r)) << 9) + (kc << 7) + (c << 4);
            uint32_t dst = sb + PSM_A + (uint32_t)(hl * 2 + buf) * 16384
                         + (uint32_t)(r << 7) + (uint32_t)((c ^ (r & 7)) << 4);
            cp16(dst, src);
        }
    };

    float oacc[4][4];
#pragma unroll
    for (int i = 0; i < 4; i++)
#pragma unroll
        for (int j = 0; j < 4; j++) oacc[i][j] = 0.0f;

    prefetch_a(0, 0);
    CP_COMMIT();
    __syncthreads();

    for (int kc = 0; kc < 4; kc++) {
        int buf = kc & 1;
        CP_WAIT0();
        __syncthreads();
        if (kc + 1 < 4) prefetch_a(buf ^ 1, kc + 1);
        CP_COMMIT();

#pragma unroll
        for (int kt = 0; kt < 4; kt++) {
            uint32_t ah[4], al[4];
            {
                int c = kt * 2 + aksel;
                uint32_t aaddr = sb + PSM_A + (uint32_t)buf * 16384
                               + amrow * 128 + ((c ^ (amrow & 7)) << 4);
                LDSM4(ah[0], ah[1], ah[2], ah[3], aaddr);
                if (three) LDSM4(al[0], al[1], al[2], al[3], aaddr + 32768);
            }
#pragma unroll
            for (int nn = 0; nn < 2; nn++) {
                uint32_t bh[4], bl[4];
                int n = f * 32 + nn * 16 + brow8;
                int c = kc * 8 + kt * 2 + bksel;
                uint32_t baddr = sb + PSM_WHI + n * 512 + ((c ^ (n & 7)) << 4);
                LDSM4(bh[0], bh[1], bh[2], bh[3], baddr);
                LDSM4(bl[0], bl[1], bl[2], bl[3], baddr + 32768);
#pragma unroll
                for (int j = 0; j < 2; j++) {
                    float* o = oacc[nn * 2 + j];
                    MMA_BF16(o, ah, bh[2*j], bh[2*j+1]);
                    MMA_BF16(o, ah, bl[2*j], bl[2*j+1]);
                    if (three) MMA_BF16(o, al, bh[2*j], bh[2*j+1]);
                }
            }
        }
    }

    int pos = tok0 - b * NT;
    if (mode == 0) {
        int qrow = b * NF + pos + wblk * 16 + g;
#pragma unroll
        for (int nn = 0; nn < 2; nn++)
#pragma unroll
            for (int j = 0; j < 2; j++) {
                float* o = oacc[nn * 2 + j];
                int n = f * 32 + nn * 16 + j * 8 + 2 * t;
                float bi0 = bias[n], bi1 = bias[n + 1];
                *(uint32_t*)&g_q[((size_t)qrow << 6) + n] =
                    pkhf((o[0] + bi0) * 0.125f, (o[1] + bi1) * 0.125f);
                *(uint32_t*)&g_q[((size_t)(qrow + 8) << 6) + n] =
                    pkhf((o[2] + bi0) * 0.125f, (o[3] + bi1) * 0.125f);
            }
    } else if (mode == 1) {
        int krow = b * NK + (pos - NF) + wblk * 16 + g;
#pragma unroll
        for (int nn = 0; nn < 2; nn++)
#pragma unroll
            for (int j = 0; j < 2; j++) {
                float* o = oacc[nn * 2 + j];
                int n = f * 32 + nn * 16 + j * 8 + 2 * t;
                float bi0 = bias[n], bi1 = bias[n + 1];
                *(uint32_t*)&g_k[((size_t)krow << 6) + n] = pkhf(o[0] + bi0, o[1] + bi1);
                *(uint32_t*)&g_k[((size_t)(krow + 8) << 6) + n] = pkhf(o[2] + bi0, o[3] + bi1);
            }
    } else {
        __syncthreads();
        __half* vs = (__half*)(smem + PSM_A);
        int row = wblk * 16 + g;
#pragma unroll
        for (int nn = 0; nn < 2; nn++)
#pragma unroll
            for (int j = 0; j < 2; j++) {
                float* o = oacc[nn * 2 + j];
                int n = f * 32 + nn * 16 + j * 8 + 2 * t;
                float bi0 = bias[n], bi1 = bias[n + 1];
                *(uint32_t*)&vs[row * VS_PITCH + n]       = pkhf(o[0] + bi0, o[1] + bi1);
                *(uint32_t*)&vs[(row + 8) * VS_PITCH + n] = pkhf(o[2] + bi0, o[3] + bi1);
            }
        __syncthreads();
        int n = tid >> 3, part = tid & 7;
        int key0 = pos - NF;
        uint32_t pk[8];
#pragma unroll
        for (int j = 0; j < 8; j++) {
            __half a = vs[(part * 16 + 2 * j) * VS_PITCH + n];
            __half bq2 = vs[(part * 16 + 2 * j + 1) * VS_PITCH + n];
            __half2 h2v = __halves2half2(a, bq2);
            pk[j] = *(uint32_t*)&h2v;
        }
        __half* dst = g_vt + (((size_t)(b * COUT + n0 + n)) << 12) + key0 + part * 16;
        *(uint4*)dst       = make_uint4(pk[0], pk[1], pk[2], pk[3]);
        *(uint4*)(dst + 8) = make_uint4(pk[4], pk[5], pk[6], pk[7]);
    }
}

// ============================================================
// mma.sync flash attention — KT=64, all-fp16 operands
//   QK: fp16 single MMA; PV: fp16 single-term
// ============================================================
#define KT 64
#define NBLK (NK / KT)

#define SM_Q     0            /* 16384 (fp16 Q, 128B rows, swizzled) */
#define SM_K     16384        /* 2 x 8192 (fp16 K) */
#define SM_V     32768        /* 2 x 32768 (fp16 V^T, 128B rows, swizzled) */
#define SM_P     98304        /* 128 x 128B, swizzled */
#define SM_LACC  114688       /* 2 x 128 floats */
#define SM_BYTES 115712

__device__ __forceinline__ void prefetch_kv(uint32_t sb, int buf, int bb, int kb)
{
    int tid = threadIdx.x;
    {   // K: 64 rows x 8 chunks = 512, one per thread
        int r = tid >> 3, c = tid & 7;
        const char* src = (const char*)g_k
                        + (((size_t)(bb * NK + kb * KT + r)) << 7) + (c << 4);
        uint32_t dst = sb + SM_K + (uint32_t)buf * 8192
                     + (uint32_t)(r << 7) + (uint32_t)((c ^ (r & 7)) << 4);
        cp16(dst, src);
    }
#pragma unroll
    for (int i = 0; i < 4; i++) {        // V^T: 256 rows x 8 chunks
        int idx = tid + i * 512;
        int n = (idx >> 3) & 255, c = idx & 7;
        const char* src = (const char*)g_vt
                        + (((size_t)(bb * COUT + n)) << 13) + (kb << 7) + (c << 4);
        uint32_t dst = sb + SM_V + (uint32_t)buf * 32768
                     + (uint32_t)(n << 7) + (uint32_t)((c ^ (n & 7)) << 4);
        cp16(dst, src);
    }
}

__global__ __launch_bounds__(512, 1) void attn_mma_kernel(float* __restrict__ out)
{
    extern __shared__ __align__(1024) char smem[];
    uint32_t sb = smem_u32(smem);
    const int tid  = threadIdx.x;
    const int lane = tid & 31;
    const int w    = tid >> 5;
    const int wblk = w >> 1;
    const int f    = w & 1;
    const int g    = lane >> 2;
    const int t    = lane & 3;
    const int bb   = blockIdx.x >> 4;
    const int qt   = blockIdx.x & 15;

    const int amrow = wblk * 16 + ((lane >> 3) & 1) * 8 + (lane & 7);
    const int aksel = lane >> 4;
    const int brow8 = ((lane >> 4) & 1) * 8 + (lane & 7);
    const int bksel = (lane >> 3) & 1;

    // ---- stage Q (fp16) into smem, swizzled ----
#pragma unroll
    for (int i = tid; i < 1024; i += 512) {
        int r = i >> 3, c = i & 7;
        const char* src = (const char*)g_q
                        + (((size_t)(bb * NF + qt * 128 + r)) << 7) + (c << 4);
        uint4 v = *(const uint4*)src;
        *(uint4*)(smem + SM_Q + r * 128 + ((c ^ (r & 7)) << 4)) = v;
    }

    float oacc[16][4];
#pragma unroll
    for (int i = 0; i < 16; i++)
#pragma unroll
        for (int j = 0; j < 4; j++) oacc[i][j] = 0.0f;
    float lacc0 = 0.0f, lacc1 = 0.0f;

    prefetch_kv(sb, 0, bb, 0);
    CP_COMMIT();

    for (int i = 0; i < NBLK; i++) {
        int buf = i & 1;
        CP_WAIT0();
        __syncthreads();

        if (i + 1 < NBLK) prefetch_kv(sb, buf ^ 1, bb, i + 1);
        CP_COMMIT();

        // ---- QK: S[16 x 32keys] = Q * K (fp16 single term) ----
        float sacc[4][4];
#pragma unroll
        for (int nt = 0; nt < 4; nt++)
#pragma unroll
            for (int j = 0; j < 4; j++) sacc[nt][j] = 0.0f;

#pragma unroll
        for (int kt = 0; kt < 4; kt++) {
            uint32_t ah[4];
            {
                int kc = kt * 2 + aksel;
                uint32_t aaddr = sb + SM_Q + amrow * 128 + ((kc ^ (amrow & 7)) << 4);
                LDSM4(ah[0], ah[1], ah[2], ah[3], aaddr);
            }
#pragma unroll
            for (int u = 0; u < 2; u++) {
                uint32_t bh[4];
                int r  = f * 32 + u * 16 + brow8;
                int kc = kt * 2 + bksel;
                uint32_t baddr = sb + SM_K + (uint32_t)buf * 8192
                               + (r << 7) + ((kc ^ (r & 7)) << 4);
                LDSM4(bh[0], bh[1], bh[2], bh[3], baddr);
#pragma unroll
                for (int v = 0; v < 2; v++) {
                    MMA_F16H(sacc[u * 2 + v], ah, bh[2*v], bh[2*v+1]);
                }
            }
        }

        // ---- exp + fp16 store, swizzled 128B-pitch P ----
        {
            int m0 = wblk * 16 + g;
#pragma unroll
            for (int nt = 0; nt < 4; nt++) {
                float p0 = __expf(sacc[nt][0]);
                float p1 = __expf(sacc[nt][1]);
                float p2 = __expf(sacc[nt][2]);
                float p3 = __expf(sacc[nt][3]);
                lacc0 += p0 + p1;
                lacc1 += p2 + p3;
                int c = f * 4 + nt;
                *(uint32_t*)(smem + SM_P + m0 * 128
                             + ((c ^ (m0 & 7)) << 4) + 4 * t) = pkhf(p0, p1);
                *(uint32_t*)(smem + SM_P + (m0 + 8) * 128
                             + ((c ^ (m0 & 7)) << 4) + 4 * t) = pkhf(p2, p3);
            }
        }
        __syncthreads();

        // ---- PV: O[16 x 128] += P * V (fp16 single term) ----
#pragma unroll
        for (int kt = 0; kt < 4; kt++) {
            uint32_t ph[4];
            {
                int kc = kt * 2 + aksel;
                uint32_t paddr = sb + SM_P + amrow * 128 + ((kc ^ (amrow & 7)) << 4);
                LDSM4(ph[0], ph[1], ph[2], ph[3], paddr);
            }
#pragma unroll
            for (int p = 0; p < 8; p++) {
                uint32_t bh[4];
                int n  = f * 128 + p * 16 + brow8;
                int kc = kt * 2 + bksel;
                uint32_t vaddr = sb + SM_V + (uint32_t)buf * 32768
                               + (n << 7) + ((kc ^ (n & 7)) << 4);
                LDSM4(bh[0], bh[1], bh[2], bh[3], vaddr);
#pragma unroll
                for (int j = 0; j < 2; j++) {
                    MMA_F16H(oacc[p * 2 + j], ph, bh[2*j], bh[2*j+1]);
                }
            }
        }
    }

    lacc0 += __shfl_xor_sync(0xFFFFFFFFu, lacc0, 1);
    lacc0 += __shfl_xor_sync(0xFFFFFFFFu, lacc0, 2);
    lacc1 += __shfl_xor_sync(0xFFFFFFFFu, lacc1, 1);
    lacc1 += __shfl_xor_sync(0xFFFFFFFFu, lacc1, 2);
    float* LACC = (float*)(smem + SM_LACC);
    if (t == 0) {
        LACC[f * 128 + wblk * 16 + g]     = lacc0;
        LACC[f * 128 + wblk * 16 + g + 8] = lacc1;
    }
    __syncthreads();
    int m0 = wblk * 16 + g;
    float linv0 = 1.0f / (LACC[m0]     + LACC[128 + m0]);
    float linv1 = 1.0f / (LACC[m0 + 8] + LACC[128 + m0 + 8]);

    float* op = out + ((size_t)(bb * NT) + qt * 128) * COUT;
#pragma unroll
    for (int p = 0; p < 16; p++) {
        int col = f * 128 + p * 8 + 2 * t;
        float2 v0 = make_float2(oacc[p][0] * linv0, oacc[p][1] * linv0);
        float2 v1 = make_float2(oacc[p][2] * linv1, oacc[p][3] * linv1);
        *(float2*)&op[(size_t)m0 * COUT + col]       = v0;
        *(float2*)&op[(size_t)(m0 + 8) * COUT + col] = v1;
    }
}

// ============================================================
extern "C" void kernel_launch(void* const* d_in, const int* in_sizes, int n_in,
                              void* d_out, int out_size)
{
    const float* feat = (const float*)d_in[0];
    const float* Wq = (const float*)d_in[2];
    const float* bq = (const float*)d_in[3];
    const float* Wk = (const float*)d_in[4];
    const float* bk = (const float*)d_in[5];
    const float* Wv = (const float*)d_in[6];
    const float* bv = (const float*)d_in[7];
    float* out = (float*)d_out;

    cudaFuncSetAttribute(attn_mma_kernel, cudaFuncAttributeMaxDynamicSharedMemorySize, SM_BYTES);
    cudaFuncSetAttribute(proj_mma_kernel, cudaFuncAttributeMaxDynamicSharedMemorySize, PSM_BYTES);

    convert_copy_kernel<<<6144, 512>>>(feat, out);
    proj_mma_kernel<<<1408, 512, PSM_BYTES>>>(Wq, bq, Wk, bk, Wv, bv);
    attn_mma_kernel<<<BATCH * (NF / 128), 512, SM_BYTES>>>(out);
}